// round 10
// baseline (speedup 1.0000x reference)
#include <cuda_runtime.h>
#include <cuda_fp16.h>
#include <math.h>

#define NN   50000
#define EE   800000
#define MM   (EE + NN)        // edges incl. self loops = 850000
#define DIM  128
#define NEG_SLOPE 0.2f
#define LN_EPS 1e-5f
#define NBLK ((NN + 255) / 256)   // 196 scan blocks

// ---- device scratch (allowed: __device__ globals, no runtime alloc) ----
__device__ __half g_xlh[NN * DIM];   // 12.8 MB  x@W_l + b_l  (fp16)
__device__ float  g_xr[NN * DIM];    // 25.6 MB  x@W_r + b_r
__device__ int    g_cnt[NN];
__device__ int    g_off[NN];
__device__ int    g_cur[NN];
__device__ int    g_bsum[256];
__device__ int    g_esrc[MM + 8];    // edge sources grouped by dst (padded)
// B fragments for mma.sync m16n8k8 tf32 (hi only; A carries the split):
__device__ float2 g_bpack2[16 * 32 * 32];   // 128 KB

// ---------------- counting sort of edges by destination -----------------

__global__ void k_init_cnt() {
    int i = blockIdx.x * blockDim.x + threadIdx.x;
    if (i < NN) g_cnt[i] = 1;        // 1 = the self loop
}

// edge_index is int32: row 0 = src[E], row 1 = dst[E]
__global__ void k_hist(const int* __restrict__ ei) {
    int e = blockIdx.x * blockDim.x + threadIdx.x;
    if (e < EE) atomicAdd(&g_cnt[ei[EE + e]], 1);
}

__global__ void k_scan1() {
    __shared__ int sh[256];
    int tid = threadIdx.x;
    int i = blockIdx.x * 256 + tid;
    int v = (i < NN) ? g_cnt[i] : 0;
    sh[tid] = v;
    __syncthreads();
    for (int s = 128; s > 0; s >>= 1) {
        if (tid < s) sh[tid] += sh[tid + s];
        __syncthreads();
    }
    if (tid == 0) g_bsum[blockIdx.x] = sh[0];
}

__global__ void k_scan2() {
    __shared__ int sh[256];
    int tid = threadIdx.x;
    int v = (tid < NBLK) ? g_bsum[tid] : 0;
    sh[tid] = v;
    __syncthreads();
    for (int off = 1; off < 256; off <<= 1) {
        int t = (tid >= off) ? sh[tid - off] : 0;
        __syncthreads();
        sh[tid] += t;
        __syncthreads();
    }
    if (tid < NBLK) g_bsum[tid] = sh[tid] - v;  // exclusive
}

__global__ void k_scan3() {
    __shared__ int sh[256];
    int tid = threadIdx.x;
    int i = blockIdx.x * 256 + tid;
    int v = (i < NN) ? g_cnt[i] : 0;
    sh[tid] = v;
    __syncthreads();
    for (int off = 1; off < 256; off <<= 1) {
        int t = (tid >= off) ? sh[tid - off] : 0;
        __syncthreads();
        sh[tid] += t;
        __syncthreads();
    }
    if (i < NN) {
        int o = g_bsum[blockIdx.x] + sh[tid] - v;  // exclusive prefix
        g_off[i] = o;
        g_cur[i] = o;
    }
}

__global__ void k_scatter(const int* __restrict__ ei) {
    int e = blockIdx.x * blockDim.x + threadIdx.x;
    if (e >= MM) return;
    int s, d;
    if (e < EE) { s = ei[e]; d = ei[EE + e]; }
    else        { s = d = e - EE; }                       // self loop
    int pos = atomicAdd(&g_cur[d], 1);
    g_esrc[pos] = s;
}

// ---------------------- tensor-core projections -------------------------

__device__ __forceinline__ float tf32_rna(float w) {
    unsigned u;
    asm("cvt.rna.tf32.f32 %0, %1;" : "=r"(u) : "f"(w));
    return __uint_as_float(u);
}

// Pack [Wl | Wr] (tf32-rounded) into B fragments.
__global__ void k_pack(const float* __restrict__ Wl, const float* __restrict__ Wr)
{
    int tid = blockIdx.x * blockDim.x + threadIdx.x;   // 0..16383
    int l  = tid & 31;
    int nt = (tid >> 5) & 31;
    int kt = tid >> 10;
    int k0 = kt * 8 + (l & 3);
    int n  = nt * 8 + (l >> 2);
    const float* base = (n < DIM) ? Wl : Wr;
    int col = (n < DIM) ? n : n - DIM;
    float w0 = base[k0 * DIM + col];
    float w1 = base[(k0 + 4) * DIM + col];
    float2 p;
    p.x = tf32_rna(w0);
    p.y = tf32_rna(w1);
    g_bpack2[(kt * 32 + nt) * 32 + l] = p;
}

__device__ __forceinline__ void mma_tf32(float* c, float a0, float a1, float a2, float a3,
                                         float b0, float b1)
{
    asm volatile(
        "mma.sync.aligned.m16n8k8.row.col.f32.tf32.tf32.f32 "
        "{%0,%1,%2,%3}, {%4,%5,%6,%7}, {%8,%9}, {%0,%1,%2,%3};"
        : "+f"(c[0]), "+f"(c[1]), "+f"(c[2]), "+f"(c[3])
        : "r"(__float_as_uint(a0)), "r"(__float_as_uint(a1)),
          "r"(__float_as_uint(a2)), "r"(__float_as_uint(a3)),
          "r"(__float_as_uint(b0)), "r"(__float_as_uint(b1)));
}

// C = x @ tf32([Wl|Wr]) + [bl|br], A split hi/lo (2-term).
#define XS_STRIDE 132
__global__ void __launch_bounds__(128) k_gemm_tc(
    const float* __restrict__ x,
    const float* __restrict__ bl,
    const float* __restrict__ br)
{
    __shared__ float xs[64 * XS_STRIDE];
    int tid = threadIdx.x;
    int w = tid >> 5, l = tid & 31;
    int row0 = blockIdx.x * 64;

    for (int i = tid; i < 64 * 32; i += 128) {
        int r = i >> 5, c4 = i & 31;
        float4 v;
        if (row0 + r < NN) v = *(const float4*)(x + (size_t)(row0 + r) * DIM + c4 * 4);
        else               v = make_float4(0.f, 0.f, 0.f, 0.f);
        *(float4*)(xs + r * XS_STRIDE + c4 * 4) = v;
    }
    __syncthreads();

    int rA = w * 16 + (l >> 2);
    int cA = l & 3;

#pragma unroll
    for (int h = 0; h < 2; h++) {            // 0 -> g_xlh (fp16), 1 -> g_xr
        float acc[16][4];
#pragma unroll
        for (int nt = 0; nt < 16; nt++)
#pragma unroll
            for (int q = 0; q < 4; q++) acc[nt][q] = 0.f;

        for (int kt = 0; kt < 16; kt++) {
            float a0 = xs[rA * XS_STRIDE + kt * 8 + cA];
            float a1 = xs[(rA + 8) * XS_STRIDE + kt * 8 + cA];
            float a2 = xs[rA * XS_STRIDE + kt * 8 + cA + 4];
            float a3 = xs[(rA + 8) * XS_STRIDE + kt * 8 + cA + 4];
            float ah0 = tf32_rna(a0), ah1 = tf32_rna(a1);
            float ah2 = tf32_rna(a2), ah3 = tf32_rna(a3);
            float al0 = tf32_rna(a0 - ah0), al1 = tf32_rna(a1 - ah1);
            float al2 = tf32_rna(a2 - ah2), al3 = tf32_rna(a3 - ah3);

            const float2* bp = g_bpack2 + (size_t)kt * 1024 + (h * 16) * 32 + l;
#pragma unroll
            for (int nt = 0; nt < 16; nt++) {
                float2 b = __ldg(bp + nt * 32);
                mma_tf32(acc[nt], ah0, ah1, ah2, ah3, b.x, b.y);  // hi*b
                mma_tf32(acc[nt], al0, al1, al2, al3, b.x, b.y);  // lo*b
            }
        }

        const float* bv = (h == 0) ? bl : br;
        int col = (l & 3) * 2;
        int rg0 = row0 + rA;
        int rg1 = rg0 + 8;
#pragma unroll
        for (int nt = 0; nt < 16; nt++) {
            int n = nt * 8 + col;
            float b0 = bv[n], b1 = bv[n + 1];
            if (h == 0) {
                if (rg0 < NN)
                    *(__half2*)(g_xlh + (size_t)rg0 * DIM + n) =
                        __floats2half2_rn(acc[nt][0] + b0, acc[nt][1] + b1);
                if (rg1 < NN)
                    *(__half2*)(g_xlh + (size_t)rg1 * DIM + n) =
                        __floats2half2_rn(acc[nt][2] + b0, acc[nt][3] + b1);
            } else {
                if (rg0 < NN) {
                    float2 v0; v0.x = acc[nt][0] + b0; v0.y = acc[nt][1] + b1;
                    *(float2*)(g_xr + (size_t)rg0 * DIM + n) = v0;
                }
                if (rg1 < NN) {
                    float2 v1; v1.x = acc[nt][2] + b0; v1.y = acc[nt][3] + b1;
                    *(float2*)(g_xr + (size_t)rg1 * DIM + n) = v1;
                }
            }
        }
    }
}

// ---------- fused: score + softmax (no-max) + aggregate + LN + ELU ------
// One warp per destination node, TWO edges per warp-iteration, with a
// depth-3 software pipeline: dat[u] holds data for iteration it+u,
// idx[u] holds the already-resolved source index for iteration it+3+u.
// Each lane keeps 3 outstanding 16B gathers; the index->data dependency
// is resolved 3 iterations early (index loads run 6 iterations ahead).
__global__ void __launch_bounds__(256) k_agg(
    const float* __restrict__ x,
    const float* __restrict__ att,
    const float* __restrict__ bias,
    const float* __restrict__ ln_g,
    const float* __restrict__ ln_b,
    float* __restrict__ out)
{
    int warp = threadIdx.x >> 5;
    int lane = threadIdx.x & 31;
    int q  = lane & 15;
    int hw = lane >> 4;
    int i = blockIdx.x * 8 + warp;          // dst node

    // per-lane slice [8q, 8q+8) of xr and att
    const float4 xr0 = *(const float4*)(g_xr + (size_t)i * DIM + q * 8);
    const float4 xr1 = *(const float4*)(g_xr + (size_t)i * DIM + q * 8 + 4);
    const float4 av0 = *(const float4*)(att + q * 8);
    const float4 av1 = *(const float4*)(att + q * 8 + 4);

    int beg = g_off[i];
    int cnt = g_cnt[i];                     // >= 1 (self loop)
    int nit = (cnt + 1) >> 1;

    float dsum = 0.f;
    float a0=0.f,a1=0.f,a2=0.f,a3=0.f,a4=0.f,a5=0.f,a6=0.f,a7=0.f;

    const char* xb = (const char*)g_xlh;
    // clamped edge-slot address for iteration t (half-warp hw)
#define JOF(t) (beg + (((2*(t) + hw) < cnt) ? (2*(t) + hw) : (cnt - 1)))

    uint4 dat[3];
    int idx[3];
#pragma unroll
    for (int u = 0; u < 3; u++) {
        int s0 = g_esrc[JOF(u)];
        dat[u] = *(const uint4*)(xb + ((size_t)s0 * DIM + q * 8) * 2);
    }
#pragma unroll
    for (int u = 0; u < 3; u++) idx[u] = g_esrc[JOF(3 + u)];

    for (int itb = 0; itb < nit; itb += 3) {
#pragma unroll
        for (int u = 0; u < 3; u++) {
            int it = itb + u;
            if (it >= nit) break;

            // prefetch data for it+3 (index resolved 3 iters ago)
            uint4 nxt = *(const uint4*)(xb + ((size_t)idx[u] * DIM + q * 8) * 2);
            // prefetch index for it+6 (clamped; always in-bounds)
            int nidx = g_esrc[JOF(it + 6)];

            bool valid = (2 * it + hw) < cnt;
            float2 p0 = __half22float2(*(const __half2*)&dat[u].x);
            float2 p1 = __half22float2(*(const __half2*)&dat[u].y);
            float2 p2 = __half22float2(*(const __half2*)&dat[u].z);
            float2 p3 = __half22float2(*(const __half2*)&dat[u].w);
            float c0=p0.x,c1=p0.y,c2=p1.x,c3=p1.y,c4=p2.x,c5=p2.y,c6=p3.x,c7=p3.y;

            float t0=c0+xr0.x; t0 = t0>0.f?t0:NEG_SLOPE*t0;
            float t1=c1+xr0.y; t1 = t1>0.f?t1:NEG_SLOPE*t1;
            float t2=c2+xr0.z; t2 = t2>0.f?t2:NEG_SLOPE*t2;
            float t3=c3+xr0.w; t3 = t3>0.f?t3:NEG_SLOPE*t3;
            float t4=c4+xr1.x; t4 = t4>0.f?t4:NEG_SLOPE*t4;
            float t5=c5+xr1.y; t5 = t5>0.f?t5:NEG_SLOPE*t5;
            float t6=c6+xr1.z; t6 = t6>0.f?t6:NEG_SLOPE*t6;
            float t7=c7+xr1.w; t7 = t7>0.f?t7:NEG_SLOPE*t7;

            float p = t0*av0.x + t1*av0.y + t2*av0.z + t3*av0.w
                    + t4*av1.x + t5*av1.y + t6*av1.z + t7*av1.w;
            p += __shfl_xor_sync(0xffffffffu, p, 1);
            p += __shfl_xor_sync(0xffffffffu, p, 2);
            // p = head (q/4) score, shared across the 4-lane group

            float wgt = valid ? __expf(p) : 0.f;   // bounded scores: no max
            dsum += wgt;                            // per-head denom
            a0 = fmaf(wgt, c0, a0); a1 = fmaf(wgt, c1, a1);
            a2 = fmaf(wgt, c2, a2); a3 = fmaf(wgt, c3, a3);
            a4 = fmaf(wgt, c4, a4); a5 = fmaf(wgt, c5, a5);
            a6 = fmaf(wgt, c6, a6); a7 = fmaf(wgt, c7, a7);

            dat[u] = nxt;
            idx[u] = nidx;
        }
    }
#undef JOF

    // combine half-warp partials (lane q and lane q+16 hold the same dims)
    dsum += __shfl_xor_sync(0xffffffffu, dsum, 16);
    a0 += __shfl_xor_sync(0xffffffffu, a0, 16);
    a1 += __shfl_xor_sync(0xffffffffu, a1, 16);
    a2 += __shfl_xor_sync(0xffffffffu, a2, 16);
    a3 += __shfl_xor_sync(0xffffffffu, a3, 16);
    a4 += __shfl_xor_sync(0xffffffffu, a4, 16);
    a5 += __shfl_xor_sync(0xffffffffu, a5, 16);
    a6 += __shfl_xor_sync(0xffffffffu, a6, 16);
    a7 += __shfl_xor_sync(0xffffffffu, a7, 16);

    // redistribute: lane l takes dims [4l, 4l+4) from source lane l>>1.
    int srcl = lane >> 1;
    float lo0 = __shfl_sync(0xffffffffu, a0, srcl);
    float hi0 = __shfl_sync(0xffffffffu, a4, srcl);
    float lo1 = __shfl_sync(0xffffffffu, a1, srcl);
    float hi1 = __shfl_sync(0xffffffffu, a5, srcl);
    float lo2 = __shfl_sync(0xffffffffu, a2, srcl);
    float hi2 = __shfl_sync(0xffffffffu, a6, srcl);
    float lo3 = __shfl_sync(0xffffffffu, a3, srcl);
    float hi3 = __shfl_sync(0xffffffffu, a7, srcl);
    float ds  = __shfl_sync(0xffffffffu, dsum, srcl);
    bool hi4 = lane & 1;
    float v0 = hi4 ? hi0 : lo0;
    float v1 = hi4 ? hi1 : lo1;
    float v2 = hi4 ? hi2 : lo2;
    float v3 = hi4 ? hi3 : lo3;
    float inv = 1.f / ds;

    float4 xv = *(const float4*)(x    + (size_t)i * DIM + lane * 4);
    float4 bv = *(const float4*)(bias + lane * 4);
    float o0 = v0 * inv + bv.x + xv.x;
    float o1 = v1 * inv + bv.y + xv.y;
    float o2 = v2 * inv + bv.z + xv.z;
    float o3 = v3 * inv + bv.w + xv.w;

    // LayerNorm across 128 values held by the warp
    float s1 = o0 + o1 + o2 + o3;
#pragma unroll
    for (int off = 16; off > 0; off >>= 1) s1 += __shfl_xor_sync(0xffffffffu, s1, off);
    float mu = s1 * (1.f / 128.f);
    float d0 = o0 - mu, d1 = o1 - mu, d2 = o2 - mu, d3 = o3 - mu;
    float s2 = d0 * d0 + d1 * d1 + d2 * d2 + d3 * d3;
#pragma unroll
    for (int off = 16; off > 0; off >>= 1) s2 += __shfl_xor_sync(0xffffffffu, s2, off);
    float rstd = rsqrtf(s2 * (1.f / 128.f) + LN_EPS);

    float4 gv = *(const float4*)(ln_g + lane * 4);
    float4 b2 = *(const float4*)(ln_b + lane * 4);
    float y0 = d0 * rstd * gv.x + b2.x;
    float y1 = d1 * rstd * gv.y + b2.y;
    float y2 = d2 * rstd * gv.z + b2.z;
    float y3 = d3 * rstd * gv.w + b2.w;
    y0 = y0 > 0.f ? y0 : (__expf(y0) - 1.f);
    y1 = y1 > 0.f ? y1 : (__expf(y1) - 1.f);
    y2 = y2 > 0.f ? y2 : (__expf(y2) - 1.f);
    y3 = y3 > 0.f ? y3 : (__expf(y3) - 1.f);

    float4 r; r.x = y0; r.y = y1; r.z = y2; r.w = y3;
    *(float4*)(out + (size_t)i * DIM + lane * 4) = r;
}

// ------------------------------ launch ----------------------------------
extern "C" void kernel_launch(void* const* d_in, const int* in_sizes, int n_in,
                              void* d_out, int out_size)
{
    const float* x    = (const float*)d_in[0];
    const int*   ei   = (const int*)d_in[1];     // int32 edge_index [2, E]
    const float* Wl   = (const float*)d_in[2];
    const float* bl   = (const float*)d_in[3];
    const float* Wr   = (const float*)d_in[4];
    const float* br   = (const float*)d_in[5];
    const float* att  = (const float*)d_in[6];
    const float* bias = (const float*)d_in[7];
    const float* lng  = (const float*)d_in[8];
    const float* lnb  = (const float*)d_in[9];
    float*       out  = (float*)d_out;

    // side stream for the (independent) edge sort; created once on the
    // non-capture correctness call, reused during graph capture.
    static cudaStream_t s2 = nullptr;
    static cudaEvent_t evFork = nullptr, evJoin = nullptr;
    if (s2 == nullptr) {
        cudaStreamCreateWithFlags(&s2, cudaStreamNonBlocking);
        cudaEventCreateWithFlags(&evFork, cudaEventDisableTiming);
        cudaEventCreateWithFlags(&evJoin, cudaEventDisableTiming);
    }

    // fork
    cudaEventRecord(evFork, 0);
    cudaStreamWaitEvent(s2, evFork, 0);

    // main stream: tensor-core projections
    k_pack<<<64, 256>>>(Wl, Wr);
    k_gemm_tc<<<(NN + 63) / 64, 128>>>(x, bl, br);

    // side stream: counting sort of edges by destination
    k_init_cnt<<<(NN + 255) / 256, 256, 0, s2>>>();
    k_hist<<<(EE + 255) / 256, 256, 0, s2>>>(ei);
    k_scan1<<<NBLK, 256, 0, s2>>>();
    k_scan2<<<1, 256, 0, s2>>>();
    k_scan3<<<NBLK, 256, 0, s2>>>();
    k_scatter<<<(MM + 255) / 256, 256, 0, s2>>>(ei);

    // join
    cudaEventRecord(evJoin, s2);
    cudaStreamWaitEvent(0, evJoin, 0);

    // fused attention aggregation + residual + LayerNorm + ELU
    k_agg<<<NN / 8, 256>>>(x, att, bias, lng, lnb, out);
}

// round 13
// speedup vs baseline: 1.2739x; 1.2739x over previous
#include <cuda_runtime.h>
#include <cuda_fp16.h>
#include <math.h>

#define NN   50000
#define EE   800000
#define MM   (EE + NN)        // edges incl. self loops = 850000
#define DIM  128
#define NEG_SLOPE 0.2f
#define LN_EPS 1e-5f
#define NBLK ((NN + 255) / 256)   // 196 scan blocks

// ---- device scratch (allowed: __device__ globals, no runtime alloc) ----
__device__ __half g_xlh[NN * DIM];   // 12.8 MB  x@W_l + b_l  (fp16)
__device__ __half g_xrh[NN * DIM];   // 12.8 MB  x@W_r + b_r  (fp16, scores only)
__device__ int    g_cnt[NN];
__device__ int    g_off[NN];
__device__ int    g_cur[NN];
__device__ int    g_bsum[256];
__device__ int    g_esrc[MM + 8];    // edge sources grouped by dst (padded)
// B fragments for mma.sync m16n8k8 tf32 (hi only; A carries the split):
__device__ float2 g_bpack2[16 * 32 * 32];   // 128 KB

// ---------------- counting sort of edges by destination -----------------

__global__ void k_init_cnt() {
    int i = blockIdx.x * blockDim.x + threadIdx.x;
    if (i < NN) g_cnt[i] = 1;        // 1 = the self loop
}

// edge_index is int32: row 0 = src[E], row 1 = dst[E]
__global__ void k_hist(const int* __restrict__ ei) {
    int e = blockIdx.x * blockDim.x + threadIdx.x;
    if (e < EE) atomicAdd(&g_cnt[ei[EE + e]], 1);
}

__global__ void k_scan1() {
    __shared__ int sh[256];
    int tid = threadIdx.x;
    int i = blockIdx.x * 256 + tid;
    int v = (i < NN) ? g_cnt[i] : 0;
    sh[tid] = v;
    __syncthreads();
    for (int s = 128; s > 0; s >>= 1) {
        if (tid < s) sh[tid] += sh[tid + s];
        __syncthreads();
    }
    if (tid == 0) g_bsum[blockIdx.x] = sh[0];
}

__global__ void k_scan2() {
    __shared__ int sh[256];
    int tid = threadIdx.x;
    int v = (tid < NBLK) ? g_bsum[tid] : 0;
    sh[tid] = v;
    __syncthreads();
    for (int off = 1; off < 256; off <<= 1) {
        int t = (tid >= off) ? sh[tid - off] : 0;
        __syncthreads();
        sh[tid] += t;
        __syncthreads();
    }
    if (tid < NBLK) g_bsum[tid] = sh[tid] - v;  // exclusive
}

__global__ void k_scan3() {
    __shared__ int sh[256];
    int tid = threadIdx.x;
    int i = blockIdx.x * 256 + tid;
    int v = (i < NN) ? g_cnt[i] : 0;
    sh[tid] = v;
    __syncthreads();
    for (int off = 1; off < 256; off <<= 1) {
        int t = (tid >= off) ? sh[tid - off] : 0;
        __syncthreads();
        sh[tid] += t;
        __syncthreads();
    }
    if (i < NN) {
        int o = g_bsum[blockIdx.x] + sh[tid] - v;  // exclusive prefix
        g_off[i] = o;
        g_cur[i] = o;
    }
}

__global__ void k_scatter(const int* __restrict__ ei) {
    int e = blockIdx.x * blockDim.x + threadIdx.x;
    if (e >= MM) return;
    int s, d;
    if (e < EE) { s = ei[e]; d = ei[EE + e]; }
    else        { s = d = e - EE; }                       // self loop
    int pos = atomicAdd(&g_cur[d], 1);
    g_esrc[pos] = s;
}

// ---------------------- tensor-core projections -------------------------

__device__ __forceinline__ float tf32_rna(float w) {
    unsigned u;
    asm("cvt.rna.tf32.f32 %0, %1;" : "=r"(u) : "f"(w));
    return __uint_as_float(u);
}

// Pack [Wl | Wr] (tf32-rounded) into B fragments.
__global__ void k_pack(const float* __restrict__ Wl, const float* __restrict__ Wr)
{
    int tid = blockIdx.x * blockDim.x + threadIdx.x;   // 0..16383
    int l  = tid & 31;
    int nt = (tid >> 5) & 31;
    int kt = tid >> 10;
    int k0 = kt * 8 + (l & 3);
    int n  = nt * 8 + (l >> 2);
    const float* base = (n < DIM) ? Wl : Wr;
    int col = (n < DIM) ? n : n - DIM;
    float w0 = base[k0 * DIM + col];
    float w1 = base[(k0 + 4) * DIM + col];
    float2 p;
    p.x = tf32_rna(w0);
    p.y = tf32_rna(w1);
    g_bpack2[(kt * 32 + nt) * 32 + l] = p;
}

__device__ __forceinline__ void mma_tf32(float* c, float a0, float a1, float a2, float a3,
                                         float b0, float b1)
{
    asm volatile(
        "mma.sync.aligned.m16n8k8.row.col.f32.tf32.tf32.f32 "
        "{%0,%1,%2,%3}, {%4,%5,%6,%7}, {%8,%9}, {%0,%1,%2,%3};"
        : "+f"(c[0]), "+f"(c[1]), "+f"(c[2]), "+f"(c[3])
        : "r"(__float_as_uint(a0)), "r"(__float_as_uint(a1)),
          "r"(__float_as_uint(a2)), "r"(__float_as_uint(a3)),
          "r"(__float_as_uint(b0)), "r"(__float_as_uint(b1)));
}

// C = x @ tf32([Wl|Wr]) + [bl|br].
// xl half (2-term A split: full precision pre-fp16); xr half (1-term: scores only).
#define XS_STRIDE 132
__global__ void __launch_bounds__(128) k_gemm_tc(
    const float* __restrict__ x,
    const float* __restrict__ bl,
    const float* __restrict__ br)
{
    __shared__ float xs[64 * XS_STRIDE];
    int tid = threadIdx.x;
    int w = tid >> 5, l = tid & 31;
    int row0 = blockIdx.x * 64;

    for (int i = tid; i < 64 * 32; i += 128) {
        int r = i >> 5, c4 = i & 31;
        float4 v;
        if (row0 + r < NN) v = *(const float4*)(x + (size_t)(row0 + r) * DIM + c4 * 4);
        else               v = make_float4(0.f, 0.f, 0.f, 0.f);
        *(float4*)(xs + r * XS_STRIDE + c4 * 4) = v;
    }
    __syncthreads();

    int rA = w * 16 + (l >> 2);
    int cA = l & 3;

#pragma unroll
    for (int h = 0; h < 2; h++) {            // 0 -> g_xlh, 1 -> g_xrh
        float acc[16][4];
#pragma unroll
        for (int nt = 0; nt < 16; nt++)
#pragma unroll
            for (int q = 0; q < 4; q++) acc[nt][q] = 0.f;

        for (int kt = 0; kt < 16; kt++) {
            float a0 = xs[rA * XS_STRIDE + kt * 8 + cA];
            float a1 = xs[(rA + 8) * XS_STRIDE + kt * 8 + cA];
            float a2 = xs[rA * XS_STRIDE + kt * 8 + cA + 4];
            float a3 = xs[(rA + 8) * XS_STRIDE + kt * 8 + cA + 4];
            float ah0 = tf32_rna(a0), ah1 = tf32_rna(a1);
            float ah2 = tf32_rna(a2), ah3 = tf32_rna(a3);
            float al0 = tf32_rna(a0 - ah0), al1 = tf32_rna(a1 - ah1);
            float al2 = tf32_rna(a2 - ah2), al3 = tf32_rna(a3 - ah3);

            const float2* bp = g_bpack2 + (size_t)kt * 1024 + (h * 16) * 32 + l;
#pragma unroll
            for (int nt = 0; nt < 16; nt++) {
                float2 b = __ldg(bp + nt * 32);
                mma_tf32(acc[nt], ah0, ah1, ah2, ah3, b.x, b.y);      // hi*b
                if (h == 0)
                    mma_tf32(acc[nt], al0, al1, al2, al3, b.x, b.y);  // lo*b (xl only)
            }
        }

        const float* bv = (h == 0) ? bl : br;
        __half* dsth = (h == 0) ? g_xlh : g_xrh;
        int col = (l & 3) * 2;
        int rg0 = row0 + rA;
        int rg1 = rg0 + 8;
#pragma unroll
        for (int nt = 0; nt < 16; nt++) {
            int n = nt * 8 + col;
            float b0 = bv[n], b1 = bv[n + 1];
            if (rg0 < NN)
                *(__half2*)(dsth + (size_t)rg0 * DIM + n) =
                    __floats2half2_rn(acc[nt][0] + b0, acc[nt][1] + b1);
            if (rg1 < NN)
                *(__half2*)(dsth + (size_t)rg1 * DIM + n) =
                    __floats2half2_rn(acc[nt][2] + b0, acc[nt][3] + b1);
        }
    }
}

// ---------- fused: score + softmax (no-max) + aggregate + LN + ELU ------
// One warp per destination node; lane q = lane&15 holds row dims [8q,8q+8);
// half-warp hw owns edges j = 2*it + hw. Unroll-2 / depth-2 pipeline:
// two data buffers + two pre-resolved indices, min()-clamped slots (the
// validity mask 2*it+hw<cnt covers every clamped tail access).
// Score path in half2: leaky = hmax2(m, 0.2*m); dot via hfma2.
__global__ void __launch_bounds__(256) k_agg(
    const float* __restrict__ x,
    const float* __restrict__ att,
    const float* __restrict__ bias,
    const float* __restrict__ ln_g,
    const float* __restrict__ ln_b,
    float* __restrict__ out)
{
    int warp = threadIdx.x >> 5;
    int lane = threadIdx.x & 31;
    int q  = lane & 15;
    int hw = lane >> 4;
    int i = blockIdx.x * 8 + warp;          // dst node

    // per-lane slice [8q, 8q+8) of xr (fp16) and att (converted to half2)
    const uint4 xru = *(const uint4*)(g_xrh + (size_t)i * DIM + q * 8);
    const __half2 xh0 = *(const __half2*)&xru.x;
    const __half2 xh1 = *(const __half2*)&xru.y;
    const __half2 xh2 = *(const __half2*)&xru.z;
    const __half2 xh3 = *(const __half2*)&xru.w;
    const float4 avf0 = *(const float4*)(att + q * 8);
    const float4 avf1 = *(const float4*)(att + q * 8 + 4);
    const __half2 ah0 = __floats2half2_rn(avf0.x, avf0.y);
    const __half2 ah1 = __floats2half2_rn(avf0.z, avf0.w);
    const __half2 ah2 = __floats2half2_rn(avf1.x, avf1.y);
    const __half2 ah3 = __floats2half2_rn(avf1.z, avf1.w);
    const __half2 neg2 = __floats2half2_rn(NEG_SLOPE, NEG_SLOPE);

    int beg = g_off[i];
    int cnt = g_cnt[i];                     // >= 1 (self loop)
    int nit = (cnt + 1) >> 1;               // 2 edges per it

    float dsum = 0.f;
    float a0=0.f,a1=0.f,a2=0.f,a3=0.f,a4=0.f,a5=0.f,a6=0.f,a7=0.f;

    const char* xb = (const char*)g_xlh;
    int cm1 = cnt - 1;
#define CLA(t) (beg + min(2*(t) + hw, cm1))

    int es0 = g_esrc[CLA(0)];
    int es1 = g_esrc[CLA(1)];
    uint4 cur0 = *(const uint4*)(xb + ((size_t)es0 * DIM + q * 8) * 2);
    uint4 cur1 = *(const uint4*)(xb + ((size_t)es1 * DIM + q * 8) * 2);
    int id0 = g_esrc[CLA(2)];
    int id1 = g_esrc[CLA(3)];

    for (int it = 0; it < nit; it += 2) {
        // depth-2 data prefetch (indices resolved one group ahead)
        uint4 nxt0 = *(const uint4*)(xb + ((size_t)id0 * DIM + q * 8) * 2);
        uint4 nxt1 = *(const uint4*)(xb + ((size_t)id1 * DIM + q * 8) * 2);
        id0 = g_esrc[CLA(it + 4)];
        id1 = g_esrc[CLA(it + 5)];

#pragma unroll
        for (int u = 0; u < 2; u++) {
            uint4 d = u ? cur1 : cur0;
            bool valid = (2 * (it + u) + hw) < cnt;

            __half2 c0h = *(const __half2*)&d.x;
            __half2 c1h = *(const __half2*)&d.y;
            __half2 c2h = *(const __half2*)&d.z;
            __half2 c3h = *(const __half2*)&d.w;

            // score: m = c + xr; leaky = max(m, 0.2*m); dot with att
            __half2 m0 = __hadd2(c0h, xh0);
            __half2 m1 = __hadd2(c1h, xh1);
            __half2 m2 = __hadd2(c2h, xh2);
            __half2 m3 = __hadd2(c3h, xh3);
            __half2 t0 = __hmax2(m0, __hmul2(m0, neg2));
            __half2 t1 = __hmax2(m1, __hmul2(m1, neg2));
            __half2 t2 = __hmax2(m2, __hmul2(m2, neg2));
            __half2 t3 = __hmax2(m3, __hmul2(m3, neg2));
            __half2 sc2 = __hmul2(t0, ah0);
            sc2 = __hfma2(t1, ah1, sc2);
            sc2 = __hfma2(t2, ah2, sc2);
            sc2 = __hfma2(t3, ah3, sc2);
            float p = __low2float(sc2) + __high2float(sc2);
            p += __shfl_xor_sync(0xffffffffu, p, 1);
            p += __shfl_xor_sync(0xffffffffu, p, 2);
            // p = head (q/4) score for this half-warp's edge

            float wgt = valid ? __expf(p) : 0.f;   // bounded scores: no max
            dsum += wgt;
            float2 f0 = __half22float2(c0h);
            float2 f1 = __half22float2(c1h);
            float2 f2 = __half22float2(c2h);
            float2 f3 = __half22float2(c3h);
            a0 = fmaf(wgt, f0.x, a0); a1 = fmaf(wgt, f0.y, a1);
            a2 = fmaf(wgt, f1.x, a2); a3 = fmaf(wgt, f1.y, a3);
            a4 = fmaf(wgt, f2.x, a4); a5 = fmaf(wgt, f2.y, a5);
            a6 = fmaf(wgt, f3.x, a6); a7 = fmaf(wgt, f3.y, a7);
        }
        cur0 = nxt0;
        cur1 = nxt1;
    }
#undef CLA

    // combine half-warp partials (lane q and lane q+16 hold the same dims)
    dsum += __shfl_xor_sync(0xffffffffu, dsum, 16);
    a0 += __shfl_xor_sync(0xffffffffu, a0, 16);
    a1 += __shfl_xor_sync(0xffffffffu, a1, 16);
    a2 += __shfl_xor_sync(0xffffffffu, a2, 16);
    a3 += __shfl_xor_sync(0xffffffffu, a3, 16);
    a4 += __shfl_xor_sync(0xffffffffu, a4, 16);
    a5 += __shfl_xor_sync(0xffffffffu, a5, 16);
    a6 += __shfl_xor_sync(0xffffffffu, a6, 16);
    a7 += __shfl_xor_sync(0xffffffffu, a7, 16);

    // redistribute: lane l takes dims [4l, 4l+4) from source lane l>>1
    // (pull both halves, select with the REQUESTER's bit; pull dsum too).
    int srcl = lane >> 1;
    float lo0 = __shfl_sync(0xffffffffu, a0, srcl);
    float hi0 = __shfl_sync(0xffffffffu, a4, srcl);
    float lo1 = __shfl_sync(0xffffffffu, a1, srcl);
    float hi1 = __shfl_sync(0xffffffffu, a5, srcl);
    float lo2 = __shfl_sync(0xffffffffu, a2, srcl);
    float hi2 = __shfl_sync(0xffffffffu, a6, srcl);
    float lo3 = __shfl_sync(0xffffffffu, a3, srcl);
    float hi3 = __shfl_sync(0xffffffffu, a7, srcl);
    float ds  = __shfl_sync(0xffffffffu, dsum, srcl);
    bool hi4 = lane & 1;
    float v0 = hi4 ? hi0 : lo0;
    float v1 = hi4 ? hi1 : lo1;
    float v2 = hi4 ? hi2 : lo2;
    float v3 = hi4 ? hi3 : lo3;
    float inv = 1.f / ds;

    float4 xv = *(const float4*)(x    + (size_t)i * DIM + lane * 4);
    float4 bv = *(const float4*)(bias + lane * 4);
    float o0 = v0 * inv + bv.x + xv.x;
    float o1 = v1 * inv + bv.y + xv.y;
    float o2 = v2 * inv + bv.z + xv.z;
    float o3 = v3 * inv + bv.w + xv.w;

    // LayerNorm across 128 values held by the warp
    float s1 = o0 + o1 + o2 + o3;
#pragma unroll
    for (int off = 16; off > 0; off >>= 1) s1 += __shfl_xor_sync(0xffffffffu, s1, off);
    float mu = s1 * (1.f / 128.f);
    float d0 = o0 - mu, d1 = o1 - mu, d2 = o2 - mu, d3 = o3 - mu;
    float s2 = d0 * d0 + d1 * d1 + d2 * d2 + d3 * d3;
#pragma unroll
    for (int off = 16; off > 0; off >>= 1) s2 += __shfl_xor_sync(0xffffffffu, s2, off);
    float rstd = rsqrtf(s2 * (1.f / 128.f) + LN_EPS);

    float4 gv = *(const float4*)(ln_g + lane * 4);
    float4 b2 = *(const float4*)(ln_b + lane * 4);
    float y0 = d0 * rstd * gv.x + b2.x;
    float y1 = d1 * rstd * gv.y + b2.y;
    float y2 = d2 * rstd * gv.z + b2.z;
    float y3 = d3 * rstd * gv.w + b2.w;
    y0 = y0 > 0.f ? y0 : (__expf(y0) - 1.f);
    y1 = y1 > 0.f ? y1 : (__expf(y1) - 1.f);
    y2 = y2 > 0.f ? y2 : (__expf(y2) - 1.f);
    y3 = y3 > 0.f ? y3 : (__expf(y3) - 1.f);

    float4 r; r.x = y0; r.y = y1; r.z = y2; r.w = y3;
    *(float4*)(out + (size_t)i * DIM + lane * 4) = r;
}

// ------------------------------ launch ----------------------------------
extern "C" void kernel_launch(void* const* d_in, const int* in_sizes, int n_in,
                              void* d_out, int out_size)
{
    const float* x    = (const float*)d_in[0];
    const int*   ei   = (const int*)d_in[1];     // int32 edge_index [2, E]
    const float* Wl   = (const float*)d_in[2];
    const float* bl   = (const float*)d_in[3];
    const float* Wr   = (const float*)d_in[4];
    const float* br   = (const float*)d_in[5];
    const float* att  = (const float*)d_in[6];
    const float* bias = (const float*)d_in[7];
    const float* lng  = (const float*)d_in[8];
    const float* lnb  = (const float*)d_in[9];
    float*       out  = (float*)d_out;

    // side stream for the (independent) edge sort; created once on the
    // non-capture correctness call, reused during graph capture.
    static cudaStream_t s2 = nullptr;
    static cudaEvent_t evFork = nullptr, evJoin = nullptr;
    if (s2 == nullptr) {
        cudaStreamCreateWithFlags(&s2, cudaStreamNonBlocking);
        cudaEventCreateWithFlags(&evFork, cudaEventDisableTiming);
        cudaEventCreateWithFlags(&evJoin, cudaEventDisableTiming);
    }

    // fork
    cudaEventRecord(evFork, 0);
    cudaStreamWaitEvent(s2, evFork, 0);

    // main stream: tensor-core projections
    k_pack<<<64, 256>>>(Wl, Wr);
    k_gemm_tc<<<(NN + 63) / 64, 128>>>(x, bl, br);

    // side stream: counting sort of edges by destination
    k_init_cnt<<<(NN + 255) / 256, 256, 0, s2>>>();
    k_hist<<<(EE + 255) / 256, 256, 0, s2>>>(ei);
    k_scan1<<<NBLK, 256, 0, s2>>>();
    k_scan2<<<1, 256, 0, s2>>>();
    k_scan3<<<NBLK, 256, 0, s2>>>();
    k_scatter<<<(MM + 255) / 256, 256, 0, s2>>>(ei);

    // join
    cudaEventRecord(evJoin, s2);
    cudaStreamWaitEvent(0, evJoin, 0);

    // fused attention aggregation + residual + LayerNorm + ELU
    k_agg<<<NN / 8, 256>>>(x, att, bias, lng, lnb, out);
}